// round 1
// baseline (speedup 1.0000x reference)
#include <cuda_runtime.h>
#include <cuda_bf16.h>
#include <cstdint>

// Problem constants
#define BB 64
#define SS 8192
#define DD 128      // D_DEC == D_ENC
#define UU 128
#define FF 16
#define CLIP_C 10.0f
#define BIG_NUMBER 1e9f

#define TS 128          // s-rows per block in main kernel
#define MAIN_THREADS 256

// scratch: qb[b][u] = dec_output[b] @ W1 + W1_b + W2_b
__device__ float g_qb[BB * UU];

// packed f32x2 FMA (sm_100+ PTX; 2 FMAs per issue slot)
#define FMA_F32X2(d, a, b, c) \
    asm("fma.rn.f32x2 %0, %1, %2, %3;" : "=l"(d) : "l"(a), "l"(b), "l"(c))

__device__ __forceinline__ unsigned long long bcast_f32x2(float v) {
    unsigned long long r;
    unsigned u = __float_as_uint(v);
    asm("mov.b64 %0, {%1, %1};" : "=l"(r) : "r"(u));
    return r;
}

// ---------------------------------------------------------------------------
// Kernel 0: qb[b][u] = sum_d dec[b][d]*W1[d][u] + W1_b[u] + W2_b[u]
// ---------------------------------------------------------------------------
__global__ void qb_kernel(const float* __restrict__ dec,
                          const float* __restrict__ W1w,
                          const float* __restrict__ W1b,
                          const float* __restrict__ W2b) {
    int b = blockIdx.x;
    int u = threadIdx.x;
    __shared__ float dsh[DD];
    dsh[u] = dec[b * DD + u];
    __syncthreads();
    float acc = 0.f;
#pragma unroll 8
    for (int d = 0; d < DD; d++) {
        acc += dsh[d] * W1w[d * UU + u];
    }
    g_qb[b * UU + u] = acc + W1b[u] + W2b[u];
}

// ---------------------------------------------------------------------------
// Kernel 1: main fused GEMM + tanh + V-dot + clip + mask -> logits[b][s]
// Block: (s-tile 128) x (u full 128). Threads 256 = 16 tx (cols) x 16 ty (rows).
// Thread computes 8 rows x 8 cols, accumulators packed as 4 f32x2 per row.
// ---------------------------------------------------------------------------
extern __shared__ float sm_main[];

__global__ void __launch_bounds__(MAIN_THREADS, 1)
main_kernel(const float* __restrict__ enc_out,
            const float* __restrict__ mask,
            const float* __restrict__ W2w,
            const float* __restrict__ Vw,
            const float* __restrict__ Vb,
            float* __restrict__ logits) {
    const int b  = blockIdx.y;
    const int s0 = blockIdx.x * TS;
    const int tid = threadIdx.x;
    const int tx = tid & 15;   // col group: cols tx*8 .. tx*8+7
    const int ty = tid >> 4;   // row group: rows ty*8 .. ty*8+7

    float* As = sm_main;            // [TS][DD] row-major (stride 128)
    float* Ws = sm_main + TS * DD;  // [DD][UU] row-major (stride 128)

    // Load tiles (each 16384 floats = 4096 float4)
    const float* Ag = enc_out + ((size_t)b * SS + s0) * DD;
#pragma unroll
    for (int k = 0; k < 16; k++) {
        int idx = tid + MAIN_THREADS * k;
        reinterpret_cast<float4*>(As)[idx] = reinterpret_cast<const float4*>(Ag)[idx];
        reinterpret_cast<float4*>(Ws)[idx] = reinterpret_cast<const float4*>(W2w)[idx];
    }
    __syncthreads();

    unsigned long long acc[8][4];
#pragma unroll
    for (int i = 0; i < 8; i++)
#pragma unroll
        for (int j = 0; j < 4; j++) acc[i][j] = 0ull;

#pragma unroll 1
    for (int dd = 0; dd < DD; dd += 4) {
        float4 a4[8];
#pragma unroll
        for (int i = 0; i < 8; i++)
            a4[i] = *reinterpret_cast<const float4*>(&As[(ty * 8 + i) * DD + dd]);
#pragma unroll
        for (int t = 0; t < 4; t++) {
            const ulonglong2 w01 =
                *reinterpret_cast<const ulonglong2*>(&Ws[(dd + t) * UU + tx * 8]);
            const ulonglong2 w23 =
                *reinterpret_cast<const ulonglong2*>(&Ws[(dd + t) * UU + tx * 8 + 4]);
#pragma unroll
            for (int i = 0; i < 8; i++) {
                const float* af = reinterpret_cast<const float*>(&a4[i]);
                unsigned long long ap = bcast_f32x2(af[t]);
                FMA_F32X2(acc[i][0], ap, w01.x, acc[i][0]);
                FMA_F32X2(acc[i][1], ap, w01.y, acc[i][1]);
                FMA_F32X2(acc[i][2], ap, w23.x, acc[i][2]);
                FMA_F32X2(acc[i][3], ap, w23.y, acc[i][3]);
            }
        }
    }

    // Epilogue: per-thread partial score over its 8 cols for each of 8 rows
    float qq[8], vv[8];
#pragma unroll
    for (int jj = 0; jj < 8; jj++) {
        int c = tx * 8 + jj;
        qq[jj] = g_qb[b * UU + c];
        vv[jj] = Vw[c];
    }

    float partial[8];
#pragma unroll
    for (int i = 0; i < 8; i++) {
        float p = 0.f;
#pragma unroll
        for (int j = 0; j < 4; j++) {
            unsigned long long v = acc[i][j];
            float lo = __uint_as_float((unsigned)(v & 0xffffffffull));
            float hi = __uint_as_float((unsigned)(v >> 32));
            p += vv[2 * j]     * tanhf(qq[2 * j]     + lo);
            p += vv[2 * j + 1] * tanhf(qq[2 * j + 1] + hi);
        }
        partial[i] = p;
    }

    __syncthreads();  // done reading As/Ws; reuse smem for reduction
    float* red = sm_main;  // [TS][16]
#pragma unroll
    for (int i = 0; i < 8; i++)
        red[(ty * 8 + i) * 16 + tx] = partial[i];
    __syncthreads();

    if (tid < TS) {
        int r = tid;
        float sc = Vb[0];
#pragma unroll
        for (int x = 0; x < 16; x++) sc += red[r * 16 + x];
        float lg = CLIP_C * tanhf(sc) - mask[(size_t)b * SS + s0 + r] * BIG_NUMBER;
        logits[(size_t)b * SS + s0 + r] = lg;
    }
}

// ---------------------------------------------------------------------------
// Kernel 2: per-batch softmax + argmax (first occurrence) + gather
// ---------------------------------------------------------------------------
#define SM_THREADS 512

__global__ void softmax_kernel(const float* __restrict__ logits,
                               const float* __restrict__ enc_input,
                               float* __restrict__ probs,
                               float* __restrict__ out_index,
                               float* __restrict__ gathered) {
    const int b = blockIdx.x;
    const int tid = threadIdx.x;
    const float* L = logits + (size_t)b * SS;
    float* P = probs + (size_t)b * SS;

    __shared__ float smax[SM_THREADS];
    __shared__ int   sidx[SM_THREADS];
    __shared__ float ssum[SM_THREADS];

    // local max + first-occurrence argmax (ascending s per thread)
    float bm = -3.0e38f;
    int bi = 0;
    for (int s = tid; s < SS; s += SM_THREADS) {
        float v = L[s];
        if (v > bm) { bm = v; bi = s; }
    }
    smax[tid] = bm;
    sidx[tid] = bi;
    __syncthreads();
    for (int off = SM_THREADS / 2; off > 0; off >>= 1) {
        if (tid < off) {
            float ov = smax[tid + off];
            int oi = sidx[tid + off];
            if (ov > smax[tid] || (ov == smax[tid] && oi < sidx[tid])) {
                smax[tid] = ov;
                sidx[tid] = oi;
            }
        }
        __syncthreads();
    }
    const float M = smax[0];
    const int idx = sidx[0];

    // sum of exp
    float ls = 0.f;
    for (int s = tid; s < SS; s += SM_THREADS) ls += expf(L[s] - M);
    ssum[tid] = ls;
    __syncthreads();
    for (int off = SM_THREADS / 2; off > 0; off >>= 1) {
        if (tid < off) ssum[tid] += ssum[tid + off];
        __syncthreads();
    }
    const float invZ = 1.0f / ssum[0];

    for (int s = tid; s < SS; s += SM_THREADS) P[s] = expf(L[s] - M) * invZ;

    if (tid == 0) out_index[b] = (float)idx;
    if (tid < FF)
        gathered[b * FF + tid] = enc_input[((size_t)b * SS + idx) * FF + tid];
}

// ---------------------------------------------------------------------------
// launch
// ---------------------------------------------------------------------------
extern "C" void kernel_launch(void* const* d_in, const int* in_sizes, int n_in,
                              void* d_out, int out_size) {
    const float* dec     = (const float*)d_in[0];   // [B,1,128]
    const float* enc_in  = (const float*)d_in[1];   // [B,S,16]
    const float* enc_out = (const float*)d_in[2];   // [B,S,128]
    const float* mask    = (const float*)d_in[3];   // [B,S]
    const float* W1w     = (const float*)d_in[4];   // [128,128]
    const float* W1b     = (const float*)d_in[5];   // [128]
    const float* W2w     = (const float*)d_in[6];   // [128,128]
    const float* W2b     = (const float*)d_in[7];   // [128]
    const float* Vw      = (const float*)d_in[8];   // [128,1]
    const float* Vb      = (const float*)d_in[9];   // [1]

    float* out     = (float*)d_out;
    float* logits  = out;                      // B*S
    float* probs   = out + (size_t)BB * SS;    // B*S
    float* oidx    = out + (size_t)2 * BB * SS;  // B (index as float)
    float* gath    = oidx + BB;                // B*F

    const int smem_bytes = 2 * TS * DD * (int)sizeof(float);  // 128 KB
    cudaFuncSetAttribute(main_kernel,
                         cudaFuncAttributeMaxDynamicSharedMemorySize, smem_bytes);

    qb_kernel<<<BB, UU>>>(dec, W1w, W1b, W2b);
    main_kernel<<<dim3(SS / TS, BB), MAIN_THREADS, smem_bytes>>>(
        enc_out, mask, W2w, Vw, Vb, logits);
    softmax_kernel<<<BB, SM_THREADS>>>(logits, enc_in, probs, oidx, gath);
}